// round 9
// baseline (speedup 1.0000x reference)
#include <cuda_runtime.h>
#include <cuda_bf16.h>
#include <cstdint>

#define BB 16
#define PP 96
#define TT 128
#define VV 64
#define NN 16
#define DD 128

// ---------------------------------------------------------------------------
// PTX helpers
// ---------------------------------------------------------------------------
__device__ __forceinline__ uint32_t smem_to_u32(const void* p) {
    uint32_t a;
    asm("{ .reg .u64 t; cvta.to.shared.u64 t, %1; cvt.u32.u64 %0, t; }"
        : "=r"(a) : "l"(p));
    return a;
}
__device__ __forceinline__ void ldsm4(uint32_t* r, uint32_t addr) {
    asm volatile("ldmatrix.sync.aligned.m8n8.x4.shared.b16 {%0,%1,%2,%3}, [%4];"
        : "=r"(r[0]), "=r"(r[1]), "=r"(r[2]), "=r"(r[3]) : "r"(addr));
}
__device__ __forceinline__ void mma_bf16(float* d, const uint32_t* a,
                                         const uint32_t* b) {
    asm volatile(
        "mma.sync.aligned.m16n8k16.row.col.f32.bf16.bf16.f32 "
        "{%0,%1,%2,%3}, {%4,%5,%6,%7}, {%8,%9}, {%0,%1,%2,%3};"
        : "+f"(d[0]), "+f"(d[1]), "+f"(d[2]), "+f"(d[3])
        : "r"(a[0]), "r"(a[1]), "r"(a[2]), "r"(a[3]), "r"(b[0]), "r"(b[1]));
}
#define CVT_BF2(w, xhi, xlo) \
    asm("cvt.rn.bf16x2.f32 %0, %1, %2;" : "=r"(w) : "f"(xhi), "f"(xlo))
#define CP_ASYNC16(dst, src) \
    asm volatile("cp.async.ca.shared.global [%0], [%1], 16;" :: "r"(dst), "l"(src))
#define CP_COMMIT() asm volatile("cp.async.commit_group;" ::: "memory")
#define CP_WAIT0()  asm volatile("cp.async.wait_group 0;" ::: "memory")
#define CP_WAIT1()  asm volatile("cp.async.wait_group 1;" ::: "memory")

// split fp32 pair -> hi bf16x2 word + lo residual word (low half = x0)
__device__ __forceinline__ void split2(float x0, float x1, uint32_t& h, uint32_t& l) {
    CVT_BF2(h, x1, x0);
    float f0 = __uint_as_float(h << 16);
    float f1 = __uint_as_float(h & 0xFFFF0000u);
    CVT_BF2(l, x1 - f1, x0 - f0);
}

// ---------------------------------------------------------------------------
// Scratch
// ---------------------------------------------------------------------------
__device__ uint32_t g_kbh[BB*TT*VV*64];   // projected keys hi bf16x2 (t<32 rows)
__device__ uint32_t g_kbl[BB*TT*VV*64];
__device__ uint32_t g_abh[BB*PP*VV*64];   // attn output hi bf16x2
__device__ uint32_t g_abl[BB*PP*VV*64];
__device__ uint32_t g_Wbh[2 * 128 * 64];  // [Wq, Wkv] hi bf16x2
__device__ uint32_t g_Wbl[2 * 128 * 64];

// ---------------------------------------------------------------------------
// Weight split prep (Wq, Wkv)
// ---------------------------------------------------------------------------
__global__ void w2bf(const float* __restrict__ Wq, const float* __restrict__ Wkv) {
    int w = blockIdx.y;
    const float* S = (w == 0) ? Wq : Wkv;
    int e = blockIdx.x * 256 + threadIdx.x;
    uint32_t h, l;
    split2(S[e * 2], S[e * 2 + 1], h, l);
    g_Wbh[w * 8192 + e] = h;
    g_Wbl[w * 8192 + e] = l;
}

// ===========================================================================
// attn_q: persistent (148 CTAs, 512 threads). Loads Wq+Wkv split ONCE, then
// loops (b,p) pairs: project q, project k(t=32+p), gather-attention.
// Afterwards folds the k(t<32) projection (concat rows) using resident Wkv.
// ===========================================================================
static constexpr int AQ_W    = 0;          // Wq hi/lo @0/34816, Wkv hi/lo @69632/104448
static constexpr int AQ_WQ   = 0;
static constexpr int AQ_WK   = 69632;
static constexpr int AQ_A    = 139264;     // bf16 A stage: hi 17408 + lo 17408
static constexpr int AQ_QO   = 174080;     // q fp32 64 x 528B
static constexpr int AQ_KS   = AQ_A;       // k fp32 aliases A stage (post-MMA)
static constexpr int AQ_SMEM = 207872;

static constexpr int NPAIR = BB * PP;      // 1536
static constexpr int NKT2  = 512;          // k(t<32): 512 tiles of 64 rows
static constexpr int AQ_GRID = 148;

// 16 warps: 4m x 4n over 64x128, warp tile 16x32
__device__ __forceinline__ void mma_64(uint32_t sbase, int woff, int lane,
                                       int warp_m, int warp_n, float acc[4][4]) {
    uint32_t a0 = sbase + AQ_A
                + (uint32_t)(warp_m * 16 + (lane & 15)) * 272 + ((lane >> 4) * 16);
    int bj = warp_n * 32 + (lane & 7) + ((lane >> 4) * 8);
    uint32_t b0 = sbase + woff + (uint32_t)bj * 272 + (((lane >> 3) & 1) * 16);
#pragma unroll
    for (int ks = 0; ks < 8; ks++) {
        uint32_t ah[4], al[4], bh[2][4], bl[2][4];
        ldsm4(ah, a0 + ks * 32);
        ldsm4(al, a0 + 17408 + ks * 32);
        ldsm4(bh[0], b0 + ks * 32);
        ldsm4(bh[1], b0 + 16 * 272 + ks * 32);
        ldsm4(bl[0], b0 + 34816 + ks * 32);
        ldsm4(bl[1], b0 + 34816 + 16 * 272 + ks * 32);
#pragma unroll
        for (int ni = 0; ni < 2; ni++)
#pragma unroll
            for (int s2 = 0; s2 < 2; s2++) {
                float* d = acc[2 * ni + s2];
                mma_bf16(d, ah, &bh[ni][2 * s2]);
                mma_bf16(d, ah, &bl[ni][2 * s2]);
                mma_bf16(d, al, &bh[ni][2 * s2]);
            }
    }
}

__global__ void __launch_bounds__(512, 1)
attn_q(const float* __restrict__ queries, const float* __restrict__ keys,
       const int* __restrict__ ccc,
       const float* __restrict__ bq, const float* __restrict__ bkv) {
    extern __shared__ char smem[];
    const uint32_t sbase = smem_to_u32(smem);
    int t = threadIdx.x, lane = t & 31, wid = t >> 5;
    int warp_m = wid >> 2, warp_n = wid & 3;

    // ---- load both split weights once (dense 2048 16B chunks per buffer) ----
#pragma unroll
    for (int sel = 0; sel < 2; sel++) {
        const uint32_t* wh = g_Wbh + sel * 8192;
        const uint32_t* wl = g_Wbl + sel * 8192;
        for (int c = t; c < 2048; c += 512) {
            uint32_t d = sbase + AQ_W + sel * 69632 + (c >> 4) * 272 + (c & 15) * 16;
            CP_ASYNC16(d, wh + 4 * c);
            CP_ASYNC16(d + 34816, wl + 4 * c);
        }
    }
    CP_COMMIT();

    auto convertA = [&](const float4* ap) {
#pragma unroll
        for (int i = 0; i < 4; i++) {
            int e = t + 512 * i;
            int r = e >> 5, c4 = e & 31;
            uint32_t h0, h1, l0, l1;
            split2(ap[i].x, ap[i].y, h0, l0);
            split2(ap[i].z, ap[i].w, h1, l1);
            char* dst = smem + AQ_A + r * 272 + c4 * 8;
            *(uint2*)dst = make_uint2(h0, h1);
            *(uint2*)(dst + 17408) = make_uint2(l0, l1);
        }
    };
    int ocol0 = warp_n * 32 + 2 * (lane & 3);
    int orow  = warp_m * 16 + (lane >> 2);
    auto writeO = [&](int off, float acc[4][4], const float* bias) {
#pragma unroll
        for (int nf = 0; nf < 4; nf++) {
            int col = ocol0 + nf * 8;
            float2 bv = *(const float2*)(bias + col);
            float* d = acc[nf];
            *(float2*)(smem + off + orow * 528 + col * 4) =
                make_float2(d[0] + bv.x, d[1] + bv.y);
            *(float2*)(smem + off + (orow + 8) * 528 + col * 4) =
                make_float2(d[2] + bv.x, d[3] + bv.y);
        }
    };

    // ---- prefetch first pair ----
    int pair = blockIdx.x;
    float4 ap[4], kp[4];
    if (pair < NPAIR) {
        const float4* q4p = (const float4*)queries + (size_t)pair * 2048;
        const float4* k4p = (const float4*)keys
                          + (size_t)((pair / PP) * TT + 32 + (pair % PP)) * 2048;
#pragma unroll
        for (int i = 0; i < 4; i++) ap[i] = q4p[t + 512 * i];
#pragma unroll
        for (int i = 0; i < 4; i++) kp[i] = k4p[t + 512 * i];
    }
    CP_WAIT0();
    __syncthreads();

    const float scale = 0.08838834764831845f;

    // ---- pair loop ----
    for (; pair < NPAIR; pair += AQ_GRID) {
        int b = pair / PP;

        convertA(ap);
        __syncthreads();

        float acc[4][4];
#pragma unroll
        for (int a = 0; a < 4; a++)
#pragma unroll
            for (int c = 0; c < 4; c++) acc[a][c] = 0.f;
        mma_64(sbase, AQ_WQ, lane, warp_m, warp_n, acc);
        __syncthreads();

        writeO(AQ_QO, acc, bq);
        convertA(kp);

        int nxt = pair + AQ_GRID;          // prefetch next pair
        if (nxt < NPAIR) {
            const float4* q4p = (const float4*)queries + (size_t)nxt * 2048;
            const float4* k4p = (const float4*)keys
                              + (size_t)((nxt / PP) * TT + 32 + (nxt % PP)) * 2048;
#pragma unroll
            for (int i = 0; i < 4; i++) ap[i] = q4p[t + 512 * i];
#pragma unroll
            for (int i = 0; i < 4; i++) kp[i] = k4p[t + 512 * i];
        }
        __syncthreads();

#pragma unroll
        for (int a = 0; a < 4; a++)
#pragma unroll
            for (int c = 0; c < 4; c++) acc[a][c] = 0.f;
        mma_64(sbase, AQ_WK, lane, warp_m, warp_n, acc);
        __syncthreads();                    // A stage fully consumed

        writeO(AQ_KS, acc, bkv);            // k fp32 into aliased A region
        __syncthreads();

        // -------- attention (8 threads/head) --------
        int v = t >> 3, to = t & 7;
        float4 q4[4];
#pragma unroll
        for (int j = 0; j < 4; j++)
            q4[j] = *(const float4*)(smem + AQ_QO + v * 528 + (to + 8 * j) * 16);

        const int* cv = ccc + b * (VV * NN) + v * NN;
        float S = 0.f;
        float4 o[4];
#pragma unroll
        for (int j = 0; j < 4; j++) o[j] = make_float4(0.f, 0.f, 0.f, 0.f);

#pragma unroll
        for (int n = 0; n < NN; n++) {
            int kidx = cv[n];
            const char* kr = smem + AQ_KS + kidx * 528;
            float4 kv[4];
            float dot = 0.f;
#pragma unroll
            for (int j = 0; j < 4; j++) {
                kv[j] = *(const float4*)(kr + (to + 8 * j) * 16);
                dot += q4[j].x * kv[j].x + q4[j].y * kv[j].y
                     + q4[j].z * kv[j].z + q4[j].w * kv[j].w;
            }
            dot += __shfl_xor_sync(0xffffffffu, dot, 1);
            dot += __shfl_xor_sync(0xffffffffu, dot, 2);
            dot += __shfl_xor_sync(0xffffffffu, dot, 4);
            float w = __expf(dot * scale);
            S += w;
#pragma unroll
            for (int j = 0; j < 4; j++) {
                o[j].x += w * kv[j].x;
                o[j].y += w * kv[j].y;
                o[j].z += w * kv[j].z;
                o[j].w += w * kv[j].w;
            }
        }

        float inv = 1.f / S;
        size_t row = (size_t)pair * VV + v;
        uint2* dh = (uint2*)(g_abh + row * 64);
        uint2* dl = (uint2*)(g_abl + row * 64);
#pragma unroll
        for (int j = 0; j < 4; j++) {
            uint32_t h0, h1, l0, l1;
            split2(o[j].x * inv, o[j].y * inv, h0, l0);
            split2(o[j].z * inv, o[j].w * inv, h1, l1);
            dh[to + 8 * j] = make_uint2(h0, h1);
            dl[to + 8 * j] = make_uint2(l0, l1);
        }
        __syncthreads();                    // KS read done before next convertA
    }

    // ---- k(t<32) projection tail: 512 tiles of 64 rows, Wkv resident ----
    float2 bv2[4];
#pragma unroll
    for (int nf = 0; nf < 4; nf++) bv2[nf] = *(const float2*)(bkv + ocol0 + nf * 8);

    int kt = blockIdx.x;
    float4 a2[4];
    auto ktrow = [](int kt) { return (kt >> 5) * 8192 + (kt & 31) * 64; };
    if (kt < NKT2) {
        const float4* src = (const float4*)keys + (size_t)ktrow(kt) * 32;
#pragma unroll
        for (int i = 0; i < 4; i++) a2[i] = src[t + 512 * i];
    }
    for (; kt < NKT2; kt += AQ_GRID) {
        convertA(a2);
        int nxt = kt + AQ_GRID;
        if (nxt < NKT2) {
            const float4* src = (const float4*)keys + (size_t)ktrow(nxt) * 32;
#pragma unroll
            for (int i = 0; i < 4; i++) a2[i] = src[t + 512 * i];
        }
        __syncthreads();

        float acc[4][4];
#pragma unroll
        for (int a = 0; a < 4; a++)
#pragma unroll
            for (int c = 0; c < 4; c++) acc[a][c] = 0.f;
        mma_64(sbase, AQ_WK, lane, warp_m, warp_n, acc);

        int gm = ktrow(kt);
#pragma unroll
        for (int nf = 0; nf < 4; nf++) {
            int col = ocol0 + nf * 8;
            int wi = col >> 1;
            float* d = acc[nf];
            uint32_t h, l;
            size_t r0 = (size_t)(gm + orow);
            split2(d[0] + bv2[nf].x, d[1] + bv2[nf].y, h, l);
            g_kbh[r0 * 64 + wi] = h; g_kbl[r0 * 64 + wi] = l;
            split2(d[2] + bv2[nf].x, d[3] + bv2[nf].y, h, l);
            g_kbh[(r0 + 8) * 64 + wi] = h; g_kbl[(r0 + 8) * 64 + wi] = l;
        }
        __syncthreads();
    }
}

// ===========================================================================
// gemm_out: persistent, cp.async-streamed split-bf16 A (g_kb / g_ab)
// ===========================================================================
static constexpr int OFF_BHI  = 0;
static constexpr int OFF_BLO  = 34816;
static constexpr int OFF_A    = 69632;
static constexpr int STAGE_B  = 17408;
static constexpr int GEMM_SMEM = OFF_A + 2 * STAGE_B;

static constexpr int NCTA = 296;
static constexpr int NOT_ = BB*TT*VV/32;  // 4096

__device__ __forceinline__ void load_W(char* smem, const float* __restrict__ W, int t) {
#pragma unroll
    for (int i = 0; i < 32; i++) {
        int e = t + 256 * i;
        int j = e >> 6, w = e & 63;
        float2 p = *(const float2*)(W + 2 * e);
        uint32_t h, l;
        split2(p.x, p.y, h, l);
        *(uint32_t*)(smem + OFF_BHI + j * 272 + w * 4) = h;
        *(uint32_t*)(smem + OFF_BLO + j * 272 + w * 4) = l;
    }
}

__device__ __forceinline__ void mma_stage(uint32_t sbase, int st, int lane,
                                          int warp_m, int warp_n, float acc[4][4]) {
    uint32_t a0 = sbase + OFF_A + st * STAGE_B
                + (uint32_t)(warp_m * 16 + (lane & 15)) * 272 + ((lane >> 4) * 16);
    int bj = warp_n * 32 + (lane & 7) + ((lane >> 4) * 8);
    uint32_t b0 = sbase + OFF_BHI + (uint32_t)bj * 272 + (((lane >> 3) & 1) * 16);
#pragma unroll
    for (int ks = 0; ks < 8; ks++) {
        uint32_t ah[4], al[4], bh[2][4], bl[2][4];
        ldsm4(ah, a0 + ks * 32);
        ldsm4(al, a0 + 8704 + ks * 32);
        ldsm4(bh[0], b0 + ks * 32);
        ldsm4(bh[1], b0 + 16 * 272 + ks * 32);
        ldsm4(bl[0], b0 + (OFF_BLO - OFF_BHI) + ks * 32);
        ldsm4(bl[1], b0 + (OFF_BLO - OFF_BHI) + 16 * 272 + ks * 32);
#pragma unroll
        for (int ni = 0; ni < 2; ni++)
#pragma unroll
            for (int s2 = 0; s2 < 2; s2++) {
                float* d = acc[2 * ni + s2];
                mma_bf16(d, ah, &bh[ni][2 * s2]);
                mma_bf16(d, ah, &bl[ni][2 * s2]);
                mma_bf16(d, al, &bh[ni][2 * s2]);
            }
    }
}

__global__ void __launch_bounds__(256, 2)
gemm_out(const float* __restrict__ Wout, const float* __restrict__ bout,
         float* __restrict__ out) {
    extern __shared__ char smem[];
    const uint32_t sbase = smem_to_u32(smem);
    int t = threadIdx.x, lane = t & 31, wid = t >> 5;
    int warp_m = wid >> 2, warp_n = wid & 3;

    load_W(smem, Wout, t);

    int ocol0 = warp_n * 32 + 2 * (lane & 3);
    float2 bv[4];
#pragma unroll
    for (int nf = 0; nf < 4; nf++) bv[nf] = *(const float2*)(bout + ocol0 + nf * 8);

    auto issueA = [&](int tile, int stg) {
        if (tile < NOT_) {
            int m0 = tile * 32;
            int b = m0 >> 13, tt = (m0 >> 6) & 127, v0 = m0 & 63;
            const uint32_t *sh, *sl;
            if (tt < 32) {
                sh = g_kbh + (size_t)m0 * 64;
                sl = g_kbl + (size_t)m0 * 64;
            } else {
                size_t rb = ((size_t)(b * PP + (tt - 32)) * VV + v0) * 64;
                sh = g_abh + rb;
                sl = g_abl + rb;
            }
            uint32_t dbase = sbase + OFF_A + stg * STAGE_B;
#pragma unroll
            for (int k = 0; k < 2; k++) {
                int c = t + 256 * k;
                uint32_t d = dbase + (c >> 4) * 272 + (c & 15) * 16;
                CP_ASYNC16(d, sh + 4 * c);
                CP_ASYNC16(d + 8704, sl + 4 * c);
            }
        }
        CP_COMMIT();
    };

    issueA(blockIdx.x, 0);
    issueA(blockIdx.x + NCTA, 1);

    int st = 0;
    for (int tile = blockIdx.x; tile < NOT_; tile += NCTA) {
        CP_WAIT1();
        __syncthreads();

        float acc[4][4];
#pragma unroll
        for (int a = 0; a < 4; a++)
#pragma unroll
            for (int c = 0; c < 4; c++) acc[a][c] = 0.f;
        mma_stage(sbase, st, lane, warp_m, warp_n, acc);

        int m0 = tile * 32;
        int orow = warp_m * 16 + (lane >> 2);
#pragma unroll
        for (int nf = 0; nf < 4; nf++) {
            int col = ocol0 + nf * 8;
            float* d = acc[nf];
            size_t r0 = (size_t)(m0 + orow);
            *(float2*)(out + r0 * DD + col) = make_float2(d[0] + bv[nf].x, d[1] + bv[nf].y);
            *(float2*)(out + (r0 + 8) * DD + col) = make_float2(d[2] + bv[nf].x, d[3] + bv[nf].y);
        }

        __syncthreads();
        issueA(tile + 2 * NCTA, st);
        st ^= 1;
    }
}

// ---------------------------------------------------------------------------
extern "C" void kernel_launch(void* const* d_in, const int* in_sizes, int n_in,
                              void* d_out, int out_size) {
    const float* queries = (const float*)d_in[0];
    const float* keys    = (const float*)d_in[1];
    const int*   ccc     = (const int*)  d_in[2];
    const float* Wq      = (const float*)d_in[3];
    const float* bq      = (const float*)d_in[4];
    const float* Wkv     = (const float*)d_in[5];
    const float* bkv     = (const float*)d_in[6];
    const float* Wout    = (const float*)d_in[7];
    const float* bout    = (const float*)d_in[8];
    float* out = (float*)d_out;

    static bool attr_done = false;
    if (!attr_done) {
        cudaFuncSetAttribute(attn_q,   cudaFuncAttributeMaxDynamicSharedMemorySize, AQ_SMEM);
        cudaFuncSetAttribute(gemm_out, cudaFuncAttributeMaxDynamicSharedMemorySize, GEMM_SMEM);
        attr_done = true;
    }

    w2bf<<<dim3(32, 2), 256>>>(Wq, Wkv);
    attn_q<<<AQ_GRID, 512, AQ_SMEM>>>(queries, keys, ccc, bq, bkv);
    gemm_out<<<NCTA, 256, GEMM_SMEM>>>(Wout, bout, out);
}

// round 10
// speedup vs baseline: 1.0138x; 1.0138x over previous
#include <cuda_runtime.h>
#include <cuda_bf16.h>
#include <cstdint>

#define BB 16
#define PP 96
#define TT 128
#define VV 64
#define NN 16
#define DD 128

// ---------------------------------------------------------------------------
// PTX helpers
// ---------------------------------------------------------------------------
__device__ __forceinline__ uint32_t smem_to_u32(const void* p) {
    uint32_t a;
    asm("{ .reg .u64 t; cvta.to.shared.u64 t, %1; cvt.u32.u64 %0, t; }"
        : "=r"(a) : "l"(p));
    return a;
}
__device__ __forceinline__ void ldsm4(uint32_t* r, uint32_t addr) {
    asm volatile("ldmatrix.sync.aligned.m8n8.x4.shared.b16 {%0,%1,%2,%3}, [%4];"
        : "=r"(r[0]), "=r"(r[1]), "=r"(r[2]), "=r"(r[3]) : "r"(addr));
}
__device__ __forceinline__ void mma_bf16(float* d, const uint32_t* a,
                                         const uint32_t* b) {
    asm volatile(
        "mma.sync.aligned.m16n8k16.row.col.f32.bf16.bf16.f32 "
        "{%0,%1,%2,%3}, {%4,%5,%6,%7}, {%8,%9}, {%0,%1,%2,%3};"
        : "+f"(d[0]), "+f"(d[1]), "+f"(d[2]), "+f"(d[3])
        : "r"(a[0]), "r"(a[1]), "r"(a[2]), "r"(a[3]), "r"(b[0]), "r"(b[1]));
}
#define CVT_BF2(w, xhi, xlo) \
    asm("cvt.rn.bf16x2.f32 %0, %1, %2;" : "=r"(w) : "f"(xhi), "f"(xlo))
#define CP_ASYNC16(dst, src) \
    asm volatile("cp.async.ca.shared.global [%0], [%1], 16;" :: "r"(dst), "l"(src))
#define CP_COMMIT() asm volatile("cp.async.commit_group;" ::: "memory")
#define CP_WAIT1()  asm volatile("cp.async.wait_group 1;" ::: "memory")

// split fp32 pair -> hi bf16x2 word + lo residual word (low half = x0)
__device__ __forceinline__ void split2(float x0, float x1, uint32_t& h, uint32_t& l) {
    CVT_BF2(h, x1, x0);
    float f0 = __uint_as_float(h << 16);
    float f1 = __uint_as_float(h & 0xFFFF0000u);
    CVT_BF2(l, x1 - f1, x0 - f0);
}

// ---------------------------------------------------------------------------
// Scratch
// ---------------------------------------------------------------------------
__device__ float g_q[BB*PP*VV*DD];        // projected queries fp32
__device__ float g_k[BB*TT*VV*DD];        // projected keys fp32 (t>=32 rows used)
__device__ uint32_t g_abh[BB*PP*VV*64];   // attn output hi bf16x2
__device__ uint32_t g_abl[BB*PP*VV*64];   // attn output lo
__device__ float g_W2[DD*DD];             // Wout @ Wkv (row-major [j,d])
__device__ float g_b2[DD];                // Wout @ bkv + bout

// ---------------------------------------------------------------------------
// prep: W2 = Wout @ Wkv, b2 = Wout @ bkv + bout
// ---------------------------------------------------------------------------
__global__ void prep(const float* __restrict__ Wout, const float* __restrict__ Wkv,
                     const float* __restrict__ bkv, const float* __restrict__ bout) {
    int e = blockIdx.x * 256 + threadIdx.x;   // 0..16383
    int j = e >> 7, d = e & 127;
    float acc = 0.f;
#pragma unroll 4
    for (int k = 0; k < 128; k++)
        acc += Wout[j * 128 + k] * Wkv[k * 128 + d];
    g_W2[e] = acc;
    if (e < 128) {
        float s = 0.f;
        for (int k = 0; k < 128; k++) s += Wout[e * 128 + k] * bkv[k];
        g_b2[e] = s + bout[e];
    }
}

// ===========================================================================
// Shared GEMM pieces (256 threads, 8 warps 2m x 4n, 32-row tiles)
// ===========================================================================
static constexpr int OFF_BHI  = 0;        // W hi: 128 x 272B = 34816
static constexpr int OFF_BLO  = 34816;
static constexpr int OFF_A    = 69632;    // 2 stages x (hi 8704 + lo 8704)
static constexpr int STAGE_B  = 17408;
static constexpr int GEMM_SMEM = OFF_A + 2 * STAGE_B;   // 104448

static constexpr int NCTA = 296;

// Load + split one 128x128 fp32 weight into SMEM (hi/lo, 272B row stride)
__device__ __forceinline__ void load_W(char* smem, const float* __restrict__ W, int t) {
#pragma unroll
    for (int i = 0; i < 32; i++) {
        int e = t + 256 * i;
        int j = e >> 6, w = e & 63;
        float2 p = *(const float2*)(W + 2 * e);
        uint32_t h, l;
        split2(p.x, p.y, h, l);
        *(uint32_t*)(smem + OFF_BHI + j * 272 + w * 4) = h;
        *(uint32_t*)(smem + OFF_BLO + j * 272 + w * 4) = l;
    }
}

// MMA over one 32-row A stage (8 warps: 2m x 4n, warp tile 16x32)
__device__ __forceinline__ void mma_stage(uint32_t sbase, int st, int lane,
                                          int warp_m, int warp_n, float acc[4][4]) {
    uint32_t a0 = sbase + OFF_A + st * STAGE_B
                + (uint32_t)(warp_m * 16 + (lane & 15)) * 272 + ((lane >> 4) * 16);
    int bj = warp_n * 32 + (lane & 7) + ((lane >> 4) * 8);
    uint32_t b0 = sbase + OFF_BHI + (uint32_t)bj * 272 + (((lane >> 3) & 1) * 16);
#pragma unroll
    for (int ks = 0; ks < 8; ks++) {
        uint32_t ah[4], al[4], bh[2][4], bl[2][4];
        ldsm4(ah, a0 + ks * 32);
        ldsm4(al, a0 + 8704 + ks * 32);
        ldsm4(bh[0], b0 + ks * 32);
        ldsm4(bh[1], b0 + 16 * 272 + ks * 32);
        ldsm4(bl[0], b0 + (OFF_BLO - OFF_BHI) + ks * 32);
        ldsm4(bl[1], b0 + (OFF_BLO - OFF_BHI) + 16 * 272 + ks * 32);
#pragma unroll
        for (int ni = 0; ni < 2; ni++)
#pragma unroll
            for (int s2 = 0; s2 < 2; s2++) {
                float* d = acc[2 * ni + s2];
                mma_bf16(d, ah, &bh[ni][2 * s2]);
                mma_bf16(d, ah, &bl[ni][2 * s2]);
                mma_bf16(d, al, &bh[ni][2 * s2]);
            }
    }
}

// ---------------------------------------------------------------------------
// gemm_qk: persistent 3-partition projection GEMM.
//   part 0 (CTAs [0,127)):   q = queries@Wq^T + bq   -> g_q          (3072 tiles)
//   part 1 (CTAs [127,254)): k(t>=32) = keys@Wkv^T   -> g_k          (3072 tiles)
//   part 2 (CTAs [254,296)): out(t<32) = keys@W2^T+b2 -> out DIRECT  (1024 tiles)
// Register-prefetched A, double-buffered bf16 stages.
// ---------------------------------------------------------------------------
__global__ void __launch_bounds__(256, 2)
gemm_qk(const float* __restrict__ queries, const float* __restrict__ keys,
        const float* __restrict__ Wq, const float* __restrict__ Wkv,
        const float* __restrict__ bq, const float* __restrict__ bkv,
        float* __restrict__ out) {
    extern __shared__ char smem[];
    const uint32_t sbase = smem_to_u32(smem);
    int t = threadIdx.x, lane = t & 31, wid = t >> 5;
    int warp_m = wid >> 2, warp_n = wid & 3;

    int cta = blockIdx.x;
    int part, tile, step, nt;
    if (cta < 127)       { part = 0; tile = cta;       step = 127; nt = 3072; }
    else if (cta < 254)  { part = 1; tile = cta - 127; step = 127; nt = 3072; }
    else                 { part = 2; tile = cta - 254; step = 42;  nt = 1024; }

    const float* X    = (part == 0) ? queries : keys;
    const float* Wsrc = (part == 0) ? Wq : (part == 1) ? Wkv : (const float*)g_W2;
    const float* bias = (part == 0) ? bq : (part == 1) ? bkv : (const float*)g_b2;
    float* Y          = (part == 0) ? g_q : (part == 1) ? g_k : out;

    load_W(smem, Wsrc, t);

    auto rowof = [&](int tl) -> int {
        if (part == 0) return tl * 32;
        if (part == 1) return (tl / 192) * 8192 + 2048 + (tl % 192) * 32;
        return (tl / 64) * 8192 + (tl % 64) * 32;
    };

    int ocol0 = warp_n * 32 + 2 * (lane & 3);
    float2 bv[4];
#pragma unroll
    for (int nf = 0; nf < 4; nf++) bv[nf] = *(const float2*)(bias + ocol0 + nf * 8);

    float4 ap[4];
    if (tile < nt) {
        const float4* src = (const float4*)(X + (size_t)rowof(tile) * DD);
#pragma unroll
        for (int i = 0; i < 4; i++) ap[i] = src[t + 256 * i];
    }

    int st = 0;
    for (; tile < nt; tile += step) {
        // convert prefetched A -> bf16 split stage st
#pragma unroll
        for (int i = 0; i < 4; i++) {
            int e = t + 256 * i;
            int r = e >> 5, w = e & 31;
            uint32_t h0, h1, l0, l1;
            split2(ap[i].x, ap[i].y, h0, l0);
            split2(ap[i].z, ap[i].w, h1, l1);
            char* p = smem + OFF_A + st * STAGE_B + r * 272 + w * 8;
            *(uint2*)p = make_uint2(h0, h1);
            *(uint2*)(p + 8704) = make_uint2(l0, l1);
        }
        __syncthreads();

        int nxt = tile + step;                 // prefetch next tile
        if (nxt < nt) {
            const float4* src = (const float4*)(X + (size_t)rowof(nxt) * DD);
#pragma unroll
            for (int i = 0; i < 4; i++) ap[i] = src[t + 256 * i];
        }

        float acc[4][4];
#pragma unroll
        for (int a = 0; a < 4; a++)
#pragma unroll
            for (int c = 0; c < 4; c++) acc[a][c] = 0.f;
        mma_stage(sbase, st, lane, warp_m, warp_n, acc);

        int gm = rowof(tile);
        int orow = warp_m * 16 + (lane >> 2);
#pragma unroll
        for (int nf = 0; nf < 4; nf++) {
            int col = ocol0 + nf * 8;
            float* d = acc[nf];
            size_t r0 = (size_t)(gm + orow);
            *(float2*)(Y + r0 * DD + col) = make_float2(d[0] + bv[nf].x, d[1] + bv[nf].y);
            *(float2*)(Y + (r0 + 8) * DD + col) = make_float2(d[2] + bv[nf].x, d[3] + bv[nf].y);
        }
        st ^= 1;
    }
}

// ---------------------------------------------------------------------------
// Attention: block per (b, p), 512 threads, 8 threads/head.
// Writes output as split hi/lo bf16 for the out-projection.
// ---------------------------------------------------------------------------
__global__ void __launch_bounds__(512, 2)
attn_kernel(const int* __restrict__ ccc) {
    __shared__ float ks[VV * 132];

    int bp = blockIdx.x;
    int b = bp / PP, p = bp % PP;
    int t = threadIdx.x;

    const float* ksrc = g_k + ((size_t)(b * TT + 32 + p) * VV) * DD;
#pragma unroll
    for (int i = 0; i < 16; i++) {
        int e = t + 512 * i;
        int v = e >> 7, d = e & 127;
        ks[v * 132 + d] = ksrc[e];
    }
    __syncthreads();

    int v = t >> 3, to = t & 7;

    const float4* qrow = (const float4*)(g_q + ((size_t)bp * VV + v) * DD);
    float4 q4[4];
#pragma unroll
    for (int j = 0; j < 4; j++) q4[j] = qrow[to + 8 * j];

    const int* cv = ccc + b * (VV * NN) + v * NN;
    const float scale = 0.08838834764831845f;

    float S = 0.f;
    float4 o[4];
#pragma unroll
    for (int j = 0; j < 4; j++) o[j] = make_float4(0.f, 0.f, 0.f, 0.f);

#pragma unroll
    for (int n = 0; n < NN; n++) {
        int kidx = cv[n];
        const float4* kr = (const float4*)(ks + kidx * 132);
        float4 kv[4];
        float dot = 0.f;
#pragma unroll
        for (int j = 0; j < 4; j++) {
            kv[j] = kr[to + 8 * j];
            dot += q4[j].x * kv[j].x + q4[j].y * kv[j].y
                 + q4[j].z * kv[j].z + q4[j].w * kv[j].w;
        }
        dot += __shfl_xor_sync(0xffffffffu, dot, 1);
        dot += __shfl_xor_sync(0xffffffffu, dot, 2);
        dot += __shfl_xor_sync(0xffffffffu, dot, 4);
        float w = __expf(dot * scale);
        S += w;
#pragma unroll
        for (int j = 0; j < 4; j++) {
            o[j].x += w * kv[j].x;
            o[j].y += w * kv[j].y;
            o[j].z += w * kv[j].z;
            o[j].w += w * kv[j].w;
        }
    }

    float inv = 1.f / S;
    size_t row = (size_t)bp * VV + v;
    uint2* dh = (uint2*)(g_abh + row * 64);
    uint2* dl = (uint2*)(g_abl + row * 64);
#pragma unroll
    for (int j = 0; j < 4; j++) {
        uint32_t h0, h1, l0, l1;
        split2(o[j].x * inv, o[j].y * inv, h0, l0);
        split2(o[j].z * inv, o[j].w * inv, h1, l1);
        dh[to + 8 * j] = make_uint2(h0, h1);
        dl[to + 8 * j] = make_uint2(l0, l1);
    }
}

// ---------------------------------------------------------------------------
// gemm_out: persistent, cp.async-streamed split-bf16 A. ONLY t>=32 rows now
// (3072 tiles): out(b, 32+p, v) = attn_out(b,p,v) @ Wout^T + bout.
// ---------------------------------------------------------------------------
static constexpr int NOT_ = 3072;

__global__ void __launch_bounds__(256, 2)
gemm_out(const float* __restrict__ Wout, const float* __restrict__ bout,
         float* __restrict__ out) {
    extern __shared__ char smem[];
    const uint32_t sbase = smem_to_u32(smem);
    int t = threadIdx.x, lane = t & 31, wid = t >> 5;
    int warp_m = wid >> 2, warp_n = wid & 3;

    load_W(smem, Wout, t);

    int ocol0 = warp_n * 32 + 2 * (lane & 3);
    float2 bv[4];
#pragma unroll
    for (int nf = 0; nf < 4; nf++) bv[nf] = *(const float2*)(bout + ocol0 + nf * 8);

    auto issueA = [&](int tile, int stg) {
        if (tile < NOT_) {
            size_t arow = (size_t)(tile / 192) * 6144 + (tile % 192) * 32;
            const uint32_t* sh = g_abh + arow * 64;
            const uint32_t* sl = g_abl + arow * 64;
            uint32_t dbase = sbase + OFF_A + stg * STAGE_B;
#pragma unroll
            for (int k = 0; k < 2; k++) {
                int c = t + 256 * k;
                uint32_t d = dbase + (c >> 4) * 272 + (c & 15) * 16;
                CP_ASYNC16(d, sh + 4 * c);
                CP_ASYNC16(d + 8704, sl + 4 * c);
            }
        }
        CP_COMMIT();
    };

    issueA(blockIdx.x, 0);
    issueA(blockIdx.x + NCTA, 1);

    int st = 0;
    for (int tile = blockIdx.x; tile < NOT_; tile += NCTA) {
        CP_WAIT1();
        __syncthreads();

        float acc[4][4];
#pragma unroll
        for (int a = 0; a < 4; a++)
#pragma unroll
            for (int c = 0; c < 4; c++) acc[a][c] = 0.f;
        mma_stage(sbase, st, lane, warp_m, warp_n, acc);

        int m0 = (tile / 192) * 8192 + 2048 + (tile % 192) * 32;
        int orow = warp_m * 16 + (lane >> 2);
#pragma unroll
        for (int nf = 0; nf < 4; nf++) {
            int col = ocol0 + nf * 8;
            float* d = acc[nf];
            size_t r0 = (size_t)(m0 + orow);
            *(float2*)(out + r0 * DD + col) = make_float2(d[0] + bv[nf].x, d[1] + bv[nf].y);
            *(float2*)(out + (r0 + 8) * DD + col) = make_float2(d[2] + bv[nf].x, d[3] + bv[nf].y);
        }

        __syncthreads();
        issueA(tile + 2 * NCTA, st);
        st ^= 1;
    }
}

// ---------------------------------------------------------------------------
extern "C" void kernel_launch(void* const* d_in, const int* in_sizes, int n_in,
                              void* d_out, int out_size) {
    const float* queries = (const float*)d_in[0];
    const float* keys    = (const float*)d_in[1];
    const int*   ccc     = (const int*)  d_in[2];
    const float* Wq      = (const float*)d_in[3];
    const float* bq      = (const float*)d_in[4];
    const float* Wkv     = (const float*)d_in[5];
    const float* bkv     = (const float*)d_in[6];
    const float* Wout    = (const float*)d_in[7];
    const float* bout    = (const float*)d_in[8];
    float* out = (float*)d_out;

    static bool attr_done = false;
    if (!attr_done) {
        cudaFuncSetAttribute(gemm_qk,  cudaFuncAttributeMaxDynamicSharedMemorySize, GEMM_SMEM);
        cudaFuncSetAttribute(gemm_out, cudaFuncAttributeMaxDynamicSharedMemorySize, GEMM_SMEM);
        attr_done = true;
    }

    prep<<<64, 256>>>(Wout, Wkv, bkv, bout);
    gemm_qk<<<NCTA, 256, GEMM_SMEM>>>(queries, keys, Wq, Wkv, bq, bkv, out);
    attn_kernel<<<BB * PP, 512>>>(ccc);
    gemm_out<<<NCTA, 256, GEMM_SMEM>>>(Wout, bout, out);
}

// round 11
// speedup vs baseline: 1.1169x; 1.1017x over previous
#include <cuda_runtime.h>
#include <cuda_bf16.h>
#include <cstdint>

#define BB 16
#define PP 96
#define TT 128
#define VV 64
#define NN 16
#define DD 128

// ---------------------------------------------------------------------------
// PTX helpers
// ---------------------------------------------------------------------------
__device__ __forceinline__ uint32_t smem_to_u32(const void* p) {
    uint32_t a;
    asm("{ .reg .u64 t; cvta.to.shared.u64 t, %1; cvt.u32.u64 %0, t; }"
        : "=r"(a) : "l"(p));
    return a;
}
__device__ __forceinline__ void ldsm4(uint32_t* r, uint32_t addr) {
    asm volatile("ldmatrix.sync.aligned.m8n8.x4.shared.b16 {%0,%1,%2,%3}, [%4];"
        : "=r"(r[0]), "=r"(r[1]), "=r"(r[2]), "=r"(r[3]) : "r"(addr));
}
__device__ __forceinline__ void mma_bf16(float* d, const uint32_t* a,
                                         const uint32_t* b) {
    asm volatile(
        "mma.sync.aligned.m16n8k16.row.col.f32.bf16.bf16.f32 "
        "{%0,%1,%2,%3}, {%4,%5,%6,%7}, {%8,%9}, {%0,%1,%2,%3};"
        : "+f"(d[0]), "+f"(d[1]), "+f"(d[2]), "+f"(d[3])
        : "r"(a[0]), "r"(a[1]), "r"(a[2]), "r"(a[3]), "r"(b[0]), "r"(b[1]));
}
#define CVT_BF2(w, xhi, xlo) \
    asm("cvt.rn.bf16x2.f32 %0, %1, %2;" : "=r"(w) : "f"(xhi), "f"(xlo))
#define CP_ASYNC16(dst, src) \
    asm volatile("cp.async.ca.shared.global [%0], [%1], 16;" :: "r"(dst), "l"(src))
#define CP_COMMIT() asm volatile("cp.async.commit_group;" ::: "memory")
#define CP_WAIT0()  asm volatile("cp.async.wait_group 0;" ::: "memory")
#define CP_WAIT1()  asm volatile("cp.async.wait_group 1;" ::: "memory")

// split fp32 pair -> hi bf16x2 word + lo residual word (low half = x0)
__device__ __forceinline__ void split2(float x0, float x1, uint32_t& h, uint32_t& l) {
    CVT_BF2(h, x1, x0);
    float f0 = __uint_as_float(h << 16);
    float f1 = __uint_as_float(h & 0xFFFF0000u);
    CVT_BF2(l, x1 - f1, x0 - f0);
}

// ---------------------------------------------------------------------------
// Scratch
// ---------------------------------------------------------------------------
__device__ float g_q[BB*PP*VV*DD];        // projected queries fp32
__device__ float g_k[BB*TT*VV*DD];        // projected keys fp32 (t>=32 rows used)
__device__ uint32_t g_kbh[BB*TT*VV*64];   // projected keys hi bf16x2 (t<32 rows)
__device__ uint32_t g_kbl[BB*TT*VV*64];

// ---------------------------------------------------------------------------
// Generic split-bf16 warp-tile MMA over a 272B-stride A stage + resident W.
// Computes a 16x32 warp tile at (warp_m, warp_n): 8 K-steps x {hh, hl, lh}.
// a_lo_off: byte offset from A hi to A lo. W lo fixed at w_base + 34816.
// ---------------------------------------------------------------------------
__device__ __forceinline__ void mma_tile(uint32_t a_base, int a_lo_off,
                                         uint32_t w_base, int lane,
                                         int warp_m, int warp_n, float acc[4][4]) {
    uint32_t a0 = a_base + (uint32_t)(warp_m * 16 + (lane & 15)) * 272
                + ((lane >> 4) * 16);
    int bj = warp_n * 32 + (lane & 7) + ((lane >> 4) * 8);
    uint32_t b0 = w_base + (uint32_t)bj * 272 + (((lane >> 3) & 1) * 16);
#pragma unroll
    for (int ks = 0; ks < 8; ks++) {
        uint32_t ah[4], al[4], bh[2][4], bl[2][4];
        ldsm4(ah, a0 + ks * 32);
        ldsm4(al, a0 + a_lo_off + ks * 32);
        ldsm4(bh[0], b0 + ks * 32);
        ldsm4(bh[1], b0 + 16 * 272 + ks * 32);
        ldsm4(bl[0], b0 + 34816 + ks * 32);
        ldsm4(bl[1], b0 + 34816 + 16 * 272 + ks * 32);
#pragma unroll
        for (int ni = 0; ni < 2; ni++)
#pragma unroll
            for (int s2 = 0; s2 < 2; s2++) {
                float* d = acc[2 * ni + s2];
                mma_bf16(d, ah, &bh[ni][2 * s2]);
                mma_bf16(d, ah, &bl[ni][2 * s2]);
                mma_bf16(d, al, &bh[ni][2 * s2]);
            }
    }
}

// ===========================================================================
// gemm_qk (round-6 form, measured 76.3us): persistent q/k projection.
// CTAs [0,127) queries, [127,296) keys. 32-row tiles, 256 threads, 8 warps.
// k rows t<32 -> split bf16 g_kb; t>=32 -> fp32 g_k.
// ===========================================================================
static constexpr int OFF_BHI  = 0;
static constexpr int OFF_BLO  = 34816;
static constexpr int OFF_A    = 69632;
static constexpr int STAGE_B  = 17408;
static constexpr int GEMM_SMEM = OFF_A + 2 * STAGE_B;   // 104448

static constexpr int NCTA = 296;
static constexpr int NQC  = 127;
static constexpr int NKC  = NCTA - NQC;   // 169
static constexpr int NQT  = BB*PP*VV/32;  // 3072
static constexpr int NKT  = BB*TT*VV/32;  // 4096

__device__ __forceinline__ void load_W256(char* smem, const float* __restrict__ W, int t) {
#pragma unroll
    for (int i = 0; i < 32; i++) {
        int e = t + 256 * i;
        int j = e >> 6, w = e & 63;
        float2 p = *(const float2*)(W + 2 * e);
        uint32_t h, l;
        split2(p.x, p.y, h, l);
        *(uint32_t*)(smem + OFF_BHI + j * 272 + w * 4) = h;
        *(uint32_t*)(smem + OFF_BLO + j * 272 + w * 4) = l;
    }
}

__global__ void __launch_bounds__(256, 2)
gemm_qk(const float* __restrict__ queries, const float* __restrict__ keys,
        const float* __restrict__ Wq, const float* __restrict__ Wkv,
        const float* __restrict__ bq, const float* __restrict__ bkv) {
    extern __shared__ char smem[];
    const uint32_t sbase = smem_to_u32(smem);
    int t = threadIdx.x, lane = t & 31, wid = t >> 5;
    int warp_m = wid >> 2, warp_n = wid & 3;
    int cta = blockIdx.x;
    bool isq = cta < NQC;
    int tile  = isq ? cta : cta - NQC;
    int tstep = isq ? NQC : NKC;
    int NT    = isq ? NQT : NKT;
    const float* X    = isq ? queries : keys;
    const float* bias = isq ? bq : bkv;

    load_W256(smem, isq ? Wq : Wkv, t);

    int ocol0 = warp_n * 32 + 2 * (lane & 3);
    float2 bv[4];
#pragma unroll
    for (int nf = 0; nf < 4; nf++) bv[nf] = *(const float2*)(bias + ocol0 + nf * 8);

    float4 ap[4];
#pragma unroll
    for (int i = 0; i < 4; i++)
        ap[i] = ((const float4*)(X + (size_t)tile * 4096))[t + 256 * i];

    int st = 0;
    for (; tile < NT; tile += tstep) {
#pragma unroll
        for (int i = 0; i < 4; i++) {
            int e = t + 256 * i;
            int r = e >> 5, w = e & 31;
            uint32_t h0, h1, l0, l1;
            split2(ap[i].x, ap[i].y, h0, l0);
            split2(ap[i].z, ap[i].w, h1, l1);
            char* p = smem + OFF_A + st * STAGE_B + r * 272 + w * 8;
            *(uint2*)p = make_uint2(h0, h1);
            *(uint2*)(p + 8704) = make_uint2(l0, l1);
        }
        __syncthreads();

        int nxt = tile + tstep;
        if (nxt < NT) {
#pragma unroll
            for (int i = 0; i < 4; i++)
                ap[i] = ((const float4*)(X + (size_t)nxt * 4096))[t + 256 * i];
        }

        float acc[4][4];
#pragma unroll
        for (int a = 0; a < 4; a++)
#pragma unroll
            for (int c = 0; c < 4; c++) acc[a][c] = 0.f;
        mma_tile(sbase + OFF_A + st * STAGE_B, 8704, sbase + OFF_BHI,
                 lane, warp_m, warp_n, acc);

        int m0 = tile * 32;
        int orow = warp_m * 16 + (lane >> 2);
        if (isq) {
#pragma unroll
            for (int nf = 0; nf < 4; nf++) {
                int col = ocol0 + nf * 8;
                float* d = acc[nf];
                size_t r0 = (size_t)(m0 + orow);
                *(float2*)(g_q + r0 * DD + col) = make_float2(d[0] + bv[nf].x, d[1] + bv[nf].y);
                *(float2*)(g_q + (r0 + 8) * DD + col) = make_float2(d[2] + bv[nf].x, d[3] + bv[nf].y);
            }
        } else {
            int tt = (m0 >> 6) & 127;
            if (tt >= 32) {
#pragma unroll
                for (int nf = 0; nf < 4; nf++) {
                    int col = ocol0 + nf * 8;
                    float* d = acc[nf];
                    size_t r0 = (size_t)(m0 + orow);
                    *(float2*)(g_k + r0 * DD + col) = make_float2(d[0] + bv[nf].x, d[1] + bv[nf].y);
                    *(float2*)(g_k + (r0 + 8) * DD + col) = make_float2(d[2] + bv[nf].x, d[3] + bv[nf].y);
                }
            } else {
#pragma unroll
                for (int nf = 0; nf < 4; nf++) {
                    int col = ocol0 + nf * 8;
                    int wi = col >> 1;
                    float* d = acc[nf];
                    uint32_t h, l;
                    size_t r0 = (size_t)(m0 + orow);
                    split2(d[0] + bv[nf].x, d[1] + bv[nf].y, h, l);
                    g_kbh[r0 * 64 + wi] = h; g_kbl[r0 * 64 + wi] = l;
                    split2(d[2] + bv[nf].x, d[3] + bv[nf].y, h, l);
                    g_kbh[(r0 + 8) * 64 + wi] = h; g_kbl[(r0 + 8) * 64 + wi] = l;
                }
            }
        }
        st ^= 1;
    }
}

// ===========================================================================
// attn_out: fused attention + out-projection, persistent (148 CTAs x 512 thr).
// SMEM: Wout split (69632) | 2x k-tile fp32 (2x33792) | bf16 A stage (34816).
// Pairs phase: attn over (b,p) then 64x128x128 out-proj MMA direct to `out`.
// Tail phase: out rows t<32 = g_kb (split bf16) @ Wout^T + bout.
// ===========================================================================
static constexpr int F_W    = 0;
static constexpr int F_KS0  = 69632;
static constexpr int F_KS1  = 103424;
static constexpr int F_STG  = 137216;     // hi 17408 + lo 17408
static constexpr int F_SMEM = 172032;

static constexpr int NPAIR   = BB * PP;   // 1536
static constexpr int AO_GRID = 148;
static constexpr int NCHUNK  = 512;       // t<32: 1024 32-row tiles, 2 per chunk

__global__ void __launch_bounds__(512, 1)
attn_out(const int* __restrict__ ccc, const float* __restrict__ Wout,
         const float* __restrict__ bout, float* __restrict__ out) {
    extern __shared__ char smem[];
    const uint32_t sbase = smem_to_u32(smem);
    int t = threadIdx.x, lane = t & 31, wid = t >> 5;
    int warp_m = wid >> 2, warp_n = wid & 3;

    // Wout split resident (512 threads, 8192 fp32 pairs)
#pragma unroll
    for (int i = 0; i < 16; i++) {
        int e = t + 512 * i;
        int j = e >> 6, w = e & 63;
        float2 p = *(const float2*)(Wout + 2 * e);
        uint32_t h, l;
        split2(p.x, p.y, h, l);
        *(uint32_t*)(smem + F_W + j * 272 + w * 4) = h;
        *(uint32_t*)(smem + F_W + 34816 + j * 272 + w * 4) = l;
    }

    int ocol0 = warp_n * 32 + 2 * (lane & 3);
    int orow  = warp_m * 16 + (lane >> 2);
    float2 bv[4];
#pragma unroll
    for (int nf = 0; nf < 4; nf++) bv[nf] = *(const float2*)(bout + ocol0 + nf * 8);

    // k-tile cp.async: 2048 16B chunks into 528B-stride rows
    auto issueKS = [&](int pr, int buf) {
        if (pr < NPAIR) {
            const char* src = (const char*)(g_k
                + ((size_t)((pr / PP) * TT + 32 + (pr % PP)) * VV) * DD);
#pragma unroll
            for (int k = 0; k < 4; k++) {
                int c = t + 512 * k;
                uint32_t d = sbase + F_KS0 + buf * 33792 + (c >> 5) * 528 + (c & 31) * 16;
                CP_ASYNC16(d, src + c * 16);
            }
        }
        CP_COMMIT();
    };

    int pair = blockIdx.x;
    issueKS(pair, 0);
    issueKS(pair + AO_GRID, 1);

    int v = t >> 3, to = t & 7;
    float4 q4[4], qn[4];
    if (pair < NPAIR) {
        const float4* q = (const float4*)(g_q + ((size_t)pair * VV + v) * DD);
#pragma unroll
        for (int j = 0; j < 4; j++) q4[j] = q[to + 8 * j];
    }

    const float scale = 0.08838834764831845f;
    int buf = 0;

    for (; pair < NPAIR; pair += AO_GRID) {
        CP_WAIT1();
        __syncthreads();
        const char* ksb = smem + F_KS0 + buf * 33792;
        int b = pair / PP;

        // -------- attention (8 threads/head) --------
        const int* cv = ccc + b * (VV * NN) + v * NN;
        float S = 0.f;
        float4 o[4];
#pragma unroll
        for (int j = 0; j < 4; j++) o[j] = make_float4(0.f, 0.f, 0.f, 0.f);
#pragma unroll
        for (int n = 0; n < NN; n++) {
            const char* kr = ksb + cv[n] * 528;
            float4 kv[4];
            float dot = 0.f;
#pragma unroll
            for (int j = 0; j < 4; j++) {
                kv[j] = *(const float4*)(kr + (to + 8 * j) * 16);
                dot += q4[j].x * kv[j].x + q4[j].y * kv[j].y
                     + q4[j].z * kv[j].z + q4[j].w * kv[j].w;
            }
            dot += __shfl_xor_sync(0xffffffffu, dot, 1);
            dot += __shfl_xor_sync(0xffffffffu, dot, 2);
            dot += __shfl_xor_sync(0xffffffffu, dot, 4);
            float w = __expf(dot * scale);
            S += w;
#pragma unroll
            for (int j = 0; j < 4; j++) {
                o[j].x += w * kv[j].x;
                o[j].y += w * kv[j].y;
                o[j].z += w * kv[j].z;
                o[j].w += w * kv[j].w;
            }
        }
        // write attn output into bf16 split MMA stage (row = head v)
        float inv = 1.f / S;
#pragma unroll
        for (int j = 0; j < 4; j++) {
            uint32_t h0, h1, l0, l1;
            split2(o[j].x * inv, o[j].y * inv, h0, l0);
            split2(o[j].z * inv, o[j].w * inv, h1, l1);
            char* d = smem + F_STG + v * 272 + (to + 8 * j) * 8;
            *(uint2*)d = make_uint2(h0, h1);
            *(uint2*)(d + 17408) = make_uint2(l0, l1);
        }
        __syncthreads();                 // ks consumed + stage complete
        issueKS(pair + 2 * AO_GRID, buf);

        // prefetch next pair's q while MMA runs
        int np = pair + AO_GRID;
        if (np < NPAIR) {
            const float4* q = (const float4*)(g_q + ((size_t)np * VV + v) * DD);
#pragma unroll
            for (int j = 0; j < 4; j++) qn[j] = q[to + 8 * j];
        }

        // -------- out-projection MMA (16 warps, 64x128 tile) --------
        float acc[4][4];
#pragma unroll
        for (int a = 0; a < 4; a++)
#pragma unroll
            for (int c = 0; c < 4; c++) acc[a][c] = 0.f;
        mma_tile(sbase + F_STG, 17408, sbase + F_W, lane, warp_m, warp_n, acc);

        size_t ob = (size_t)b * 8192 + (size_t)(32 + pair % PP) * 64;
#pragma unroll
        for (int nf = 0; nf < 4; nf++) {
            int col = ocol0 + nf * 8;
            float* d = acc[nf];
            *(float2*)(out + (ob + orow) * DD + col) =
                make_float2(d[0] + bv[nf].x, d[1] + bv[nf].y);
            *(float2*)(out + (ob + orow + 8) * DD + col) =
                make_float2(d[2] + bv[nf].x, d[3] + bv[nf].y);
        }
#pragma unroll
        for (int j = 0; j < 4; j++) q4[j] = qn[j];
        buf ^= 1;
    }

    CP_WAIT0();
    __syncthreads();

    // -------- tail: out rows t<32 from g_kb (2 tiles of 32 rows per chunk) --
    int g2 = wid >> 3, w7 = wid & 7;
    int warp_m2 = w7 >> 2;               // warp_n2 == warp_n (wid&3) -> bv valid
    int orow2 = warp_m2 * 16 + (lane >> 2);

    for (int ch = blockIdx.x; ch < NCHUNK; ch += AO_GRID) {
        int m0a = ((2 * ch) >> 6) * 8192 + ((2 * ch) & 63) * 32;
        int m0b = ((2 * ch + 1) >> 6) * 8192 + ((2 * ch + 1) & 63) * 32;
#pragma unroll
        for (int k = 0; k < 4; k++) {
            int c = t + 512 * k;             // 0..2047
            int g = c >> 10, cc = c & 1023;
            int half = cc >> 9, cd = cc & 511;
            int row = cd >> 4, off = cd & 15;
            int m0 = g ? m0b : m0a;
            const uint32_t* src = (half ? g_kbl : g_kbh) + (size_t)(m0 + row) * 64 + off * 4;
            uint32_t d = sbase + F_STG + g * 8704 + half * 17408 + row * 272 + off * 16;
            CP_ASYNC16(d, src);
        }
        CP_COMMIT();
        CP_WAIT0();
        __syncthreads();

        float acc[4][4];
#pragma unroll
        for (int a = 0; a < 4; a++)
#pragma unroll
            for (int c = 0; c < 4; c++) acc[a][c] = 0.f;
        mma_tile(sbase + F_STG + g2 * 8704, 17408, sbase + F_W,
                 lane, warp_m2, warp_n, acc);

        int m0 = g2 ? m0b : m0a;
#pragma unroll
        for (int nf = 0; nf < 4; nf++) {
            int col = ocol0 + nf * 8;
            float* d = acc[nf];
            size_t r0 = (size_t)(m0 + orow2);
            *(float2*)(out + r0 * DD + col) =
                make_float2(d[0] + bv[nf].x, d[1] + bv[nf].y);
            *(float2*)(out + (r0 + 8) * DD + col) =
                make_float2(d[2] + bv[nf].x, d[3] + bv[nf].y);
        }
        __syncthreads();
    }
}

// ---------------------------------------------------------------------------
extern "C" void kernel_launch(void* const* d_in, const int* in_sizes, int n_in,
                              void* d_out, int out_size) {
    const float* queries = (const float*)d_in[0];
    const float* keys    = (const float*)d_in[1];
    const int*   ccc     = (const int*)  d_in[2];
    const float* Wq      = (const float*)d_in[3];
    const float* bq      = (const float*)d_in[4];
    const float* Wkv     = (const float*)d_in[5];
    const float* bkv     = (const float*)d_in[6];
    const float* Wout    = (const float*)d_in[7];
    const float* bout    = (const float*)d_in[8];
    float* out = (float*)d_out;

    static bool attr_done = false;
    if (!attr_done) {
        cudaFuncSetAttribute(gemm_qk,  cudaFuncAttributeMaxDynamicSharedMemorySize, GEMM_SMEM);
        cudaFuncSetAttribute(attn_out, cudaFuncAttributeMaxDynamicSharedMemorySize, F_SMEM);
        attr_done = true;
    }

    gemm_qk<<<NCTA, 256, GEMM_SMEM>>>(queries, keys, Wq, Wkv, bq, bkv);
    attn_out<<<AO_GRID, 512, F_SMEM>>>(ccc, Wout, bout, out);
}